// round 12
// baseline (speedup 1.0000x reference)
#include <cuda_runtime.h>
#include <cuda_bf16.h>
#include <math.h>

// Problem constants (fixed by setup_inputs)
#define BATCH 8
#define TLEN  960
#define NHARM 32
#define NSAMP 245760            // 256 * 960; radix-16 levels: 15360/960/60/4
#define NB0   15360             // NSAMP/16

// Scratch (no allocation allowed): e[], 16-block sums, blocked scan of sums
__device__ float g_e  [(size_t)BATCH * NSAMP];
__device__ float g_b0 [(size_t)BATCH * NB0];
__device__ float g_sc0[(size_t)BATCH * NB0];
__device__ int   g_maxabs[BATCH];

// ---------------------------------------------------------------------------
// Accurate sin(t) for t in [0, ~2^20), all-fp32.
// q via magic-number round of t*(2/pi); two-fma Cody-Waite reduction
// (C1 = fl(pi/2), C2 = fl(C1 - pi/2)); Taylor sin/cos on |r| <= 0.86.
// Absolute error ~2e-7 (far below the 1e-3 budget).
// ---------------------------------------------------------------------------
__device__ __forceinline__ float fast_sin_pos(float t) {
    const float MAGIC = 12582912.0f;  // 2^23 + 2^22
    float mq = __fmaf_rn(t, 0.63661977236758134308f, MAGIC);
    int   q  = __float_as_int(mq);    // low mantissa bits == q (q >= 0)
    float qf = mq - MAGIC;
    float r  = __fmaf_rn(qf, -1.57079637050628662109f, t);  // t - q*C1
    r = __fmaf_rn(qf, 4.37113882867379188e-8f, r);          // + q*(C1 - pi/2)
    float r2 = __fmul_rn(r, r);
    float sp = __fmaf_rn(2.75573192239859e-6f, r2, -1.98412698412698e-4f);
    sp = __fmaf_rn(sp, r2, 8.33333333333333e-3f);
    sp = __fmaf_rn(sp, r2, -1.66666666666667e-1f);
    float sv = __fmaf_rn(__fmul_rn(sp, r2), r, r);
    float cp = __fmaf_rn(-2.75573192239859e-7f, r2, 2.48015873015873e-5f);
    cp = __fmaf_rn(cp, r2, -1.38888888888889e-3f);
    cp = __fmaf_rn(cp, r2, 4.16666666666667e-2f);
    cp = __fmaf_rn(cp, r2, -0.5f);
    float cv = __fmaf_rn(cp, r2, 1.0f);
    float v = (q & 1) ? cv : sv;
    return (q & 2) ? -v : v;
}

// ---------------------------------------------------------------------------
// Kernel A: per (batch, 4096-chunk): e[m] = fl(interp(clip(f0))[m] * C)
// where C = fl(1/24000) — XLA's algebraic simplifier rewrites divide-by-
// constant into multiply-by-reciprocal (constant-folded in f32). Also serial
// LTR sums of each 16-block (= reduce_window row totals) -> g_b0.
// ---------------------------------------------------------------------------
__global__ void __launch_bounds__(256) kA(const float* __restrict__ f0) {
    __shared__ float se[4096];
    int b = blockIdx.y;
    int c = blockIdx.x;
    const float* f0b = f0 + (size_t)b * TLEN;
    float* eb = g_e + (size_t)b * NSAMP;
    int n0 = c * 4096;

    for (int i = threadIdx.x; i < 4096; i += 256) {
        int n = n0 + i;
        // pos = (n+0.5)/256 - 0.5 : every step exact in fp32
        float pos = __fmul_rn((float)n + 0.5f, 0.00390625f) - 0.5f;
        pos = fminf(fmaxf(pos, 0.0f), 959.0f);
        int   i0 = (int)pos;
        int   i1 = min(i0 + 1, 959);
        float w  = pos - (float)i0;       // exact
        float x0 = fminf(fmaxf(f0b[i0], 50.0f), 1000.0f);
        float x1 = fminf(fmaxf(f0b[i1], 50.0f), 1000.0f);
        float v  = __fadd_rn(__fmul_rn(x0, 1.0f - w), __fmul_rn(x1, w));
        float e  = __fmul_rn(v, (1.0f / 24000.0f));  // XLA: div -> mul recip
        se[i] = e;
        eb[n] = e;
    }
    __syncthreads();

    // 16-block serial sums: this chunk holds 256 blocks of 16
    int t = threadIdx.x;
    float acc = se[16 * t];
#pragma unroll
    for (int r = 1; r < 16; r++) acc = __fadd_rn(acc, se[16 * t + r]);
    g_b0[(size_t)b * NB0 + c * 256 + t] = acc;
}

// ---------------------------------------------------------------------------
// Kernel B: per batch — blocked radix-16 scan of the 15360 block sums,
// exactly mirroring XLA ReduceWindowRewriter(base_length=16):
//   B1[960]  = serial 16-sums of B0;  B2[60] = serial 16-sums of B1;
//   B3[4]    = serial sums of B2 16-blocks (last block 12 real + exact 0 pad)
//   SC3      = serial scan of B3 (<=16 base case, LTR)
//   SC2[j]   = LTR-inner(B2 within 16-block) (+ SC3[parent-1] if parent>0)
//   SC1, SC0 analogously; SC0 -> gmem. Right-nested prefix adds, one fadd
//   per level; first block adds nothing (reference adds exact 0).
// ---------------------------------------------------------------------------
__global__ void __launch_bounds__(256) kB() {
    __shared__ float B1[960], B2[60], B3s[4], SC3[4], SC2[60], SC1[960];
    int b = blockIdx.x;
    const float* b0 = g_b0 + (size_t)b * NB0;
    float* sc0 = g_sc0 + (size_t)b * NB0;
    int tid = threadIdx.x;

    for (int j = tid; j < 960; j += 256) {
        float a = b0[16 * j];
#pragma unroll
        for (int r = 1; r < 16; r++) a = __fadd_rn(a, b0[16 * j + r]);
        B1[j] = a;
    }
    __syncthreads();

    if (tid < 60) {
        float a = B1[16 * tid];
#pragma unroll
        for (int r = 1; r < 16; r++) a = __fadd_rn(a, B1[16 * tid + r]);
        B2[tid] = a;
    }
    __syncthreads();

    if (tid == 0) {
        for (int k = 0; k < 4; k++) {
            int hi = min(16 * k + 16, 60);       // last block: 12 real + 0-pad
            float a = B2[16 * k];
            for (int r = 16 * k + 1; r < hi; r++) a = __fadd_rn(a, B2[r]);
            B3s[k] = a;
        }
        SC3[0] = B3s[0];
        for (int k = 1; k < 4; k++) SC3[k] = __fadd_rn(SC3[k - 1], B3s[k]);
    }
    __syncthreads();

    if (tid < 60) {
        int p = tid >> 4;
        float inner = B2[16 * p];
        for (int r = 16 * p + 1; r <= tid; r++) inner = __fadd_rn(inner, B2[r]);
        SC2[tid] = p ? __fadd_rn(inner, SC3[p - 1]) : inner;
    }
    __syncthreads();

    for (int j = tid; j < 960; j += 256) {
        int p = j >> 4;
        float inner = B1[16 * p];
        for (int r = 16 * p + 1; r <= j; r++) inner = __fadd_rn(inner, B1[r]);
        SC1[j] = p ? __fadd_rn(inner, SC2[p - 1]) : inner;
    }
    __syncthreads();

    for (int j = tid; j < NB0; j += 256) {
        int p = j >> 4;
        float inner = b0[16 * p];
        for (int r = 16 * p + 1; r <= j; r++) inner = __fadd_rn(inner, b0[r]);
        sc0[j] = p ? __fadd_rn(inner, SC1[p - 1]) : inner;
    }
    if (tid == 0) g_maxabs[b] = 0;
}

// ---------------------------------------------------------------------------
// Kernel C: per (batch, 256-sample segment): phase = LTR serial within the
// sample's 16-block + one prefix add of SC0[o0-1]; 32 harmonics with
// t = fl(fl(2pi*phi)*k), accurate sin, amp interp from 3 smem frames;
// unnormalized harm out; block+atomic max.
// ---------------------------------------------------------------------------
__global__ void __launch_bounds__(256) kC(const float* __restrict__ ha,
                                          float* __restrict__ out) {
    __shared__ float se[256];
    __shared__ float scp[16];
    __shared__ float amps[3][32];
    __shared__ float smax[8];
    int b = blockIdx.y;
    int s = blockIdx.x;

    se[threadIdx.x] = g_e[(size_t)b * NSAMP + s * 256 + threadIdx.x];
    if (threadIdx.x < 16) {
        int o0 = s * 16 + threadIdx.x;
        scp[threadIdx.x] = (o0 == 0) ? 0.0f : g_sc0[(size_t)b * NB0 + o0 - 1];
    }
    if (threadIdx.x < 96) {
        int slot = threadIdx.x >> 5, k = threadIdx.x & 31;
        int t = s - 1 + slot;
        t = max(0, min(t, TLEN - 1));
        amps[slot][k] = ha[((size_t)(b * NHARM + k)) * TLEN + t];
    }
    __syncthreads();

    int i = threadIdx.x;
    int n = s * 256 + i;
    int ob = i >> 4;

    // inner serial LTR over this 16-block up to i
    float inner = se[ob << 4];
    for (int r = (ob << 4) + 1; r <= i; r++) inner = __fadd_rn(inner, se[r]);
    float phi = (s == 0 && ob == 0) ? inner : __fadd_rn(inner, scp[ob]);

    float theta = __fmul_rn(6.28318530717958647692f, phi);  // fl(2pi*phi)

    // amp interp weights (exact positions, as in f0 interp)
    float posa = __fmul_rn((float)n + 0.5f, 0.00390625f) - 0.5f;
    posa = fminf(fmaxf(posa, 0.0f), 959.0f);
    int   i0 = (int)posa;
    int   i1 = min(i0 + 1, 959);
    float w  = posa - (float)i0;
    float omw = 1.0f - w;
    int sl0 = i0 - s + 1;
    int sl1 = i1 - s + 1;

    float hsum = 0.0f;
#pragma unroll
    for (int k = 0; k < 32; ++k) {
        float t  = __fmul_rn(theta, (float)(k + 1));
        float sv = fast_sin_pos(t);
        float a  = __fadd_rn(__fmul_rn(amps[sl0][k], omw),
                             __fmul_rn(amps[sl1][k], w));
        hsum = __fadd_rn(hsum, __fmul_rn(sv, a));
    }
    out[(size_t)b * NSAMP + n] = hsum;

    float av = fabsf(hsum);
#pragma unroll
    for (int off = 16; off; off >>= 1)
        av = fmaxf(av, __shfl_xor_sync(0xffffffffu, av, off));
    if ((i & 31) == 0) smax[i >> 5] = av;
    __syncthreads();
    if (i == 0) {
        float mv = smax[0];
#pragma unroll
        for (int wv = 1; wv < 8; ++wv) mv = fmaxf(mv, smax[wv]);
        atomicMax(&g_maxabs[b], __float_as_int(mv));
    }
}

// ---------------------------------------------------------------------------
// Kernel D: out /= max(max|harm| + 1e-7, 1). (Noise path is exactly zero:
// the mel filters all collapse below the first freq bin -> filters == 0.)
// ---------------------------------------------------------------------------
__global__ void __launch_bounds__(256) kD(float* __restrict__ out) {
    int b = blockIdx.y;
    float denom = fmaxf(__fadd_rn(__int_as_float(g_maxabs[b]), 1e-7f), 1.0f);
    size_t idx = (size_t)b * NSAMP + blockIdx.x * 256 + threadIdx.x;
    out[idx] = __fdiv_rn(out[idx], denom);
}

extern "C" void kernel_launch(void* const* d_in, const int* in_sizes, int n_in,
                              void* d_out, int out_size) {
    const float* f0 = (const float*)d_in[0];
    const float* ha = (const float*)d_in[1];
    float* out = (float*)d_out;

    kA<<<dim3(60, BATCH), 256>>>(f0);
    kB<<<BATCH, 256>>>();
    kC<<<dim3(960, BATCH), 256>>>(ha, out);
    kD<<<dim3(960, BATCH), 256>>>(out);
}

// round 13
// speedup vs baseline: 1.3090x; 1.3090x over previous
#include <cuda_runtime.h>
#include <cuda_bf16.h>
#include <math.h>

// Problem constants (fixed by setup_inputs)
#define BATCH 8
#define TLEN  960
#define NHARM 32
#define NSAMP 245760            // 256 * 960; radix-16 scan levels: 15360/960/60/4
#define NB0   15360             // NSAMP/16

// Scratch (no allocation allowed): 16-block sums + their blocked scan
__device__ float g_b0 [(size_t)BATCH * NB0];
__device__ float g_sc0[(size_t)BATCH * NB0];
__device__ int   g_maxabs[BATCH];

// ---------------------------------------------------------------------------
// Accurate sin(t) for t in [0, ~2^20), all-fp32, pi-based reduction.
// q = rint(t/pi) via magic-number (t/pi < 2^22); two-fma Cody-Waite
// (C1 = fl(pi), -C2 = fl(pi) - pi = 8.742277657e-8); sign fold by parity of q
// (integer XOR, ALU pipe); degree-11 odd Taylor on |r| <= 1.585
// (poly remainder ~6e-8, reduction rounding ~2.5e-7). Total abs err ~3e-7.
// ---------------------------------------------------------------------------
__device__ __forceinline__ float fast_sin_pos(float t) {
    const float MAGIC = 12582912.0f;  // 2^23 + 2^22
    float mq = __fmaf_rn(t, 0.31830988618379067154f, MAGIC);
    int   qi = __float_as_int(mq);    // low mantissa bits == q (q >= 0)
    float qf = mq - MAGIC;
    float r  = __fmaf_rn(qf, -3.14159274101257324219f, t);   // t - q*C1
    r = __fmaf_rn(qf, 8.74227765734758577e-8f, r);           // + q*(C1 - pi)
    r = __int_as_float(__float_as_int(r) ^ (qi << 31));      // (-1)^q * r
    float r2 = __fmul_rn(r, r);
    float p  = __fmaf_rn(-2.50521083854417188e-8f, r2, 2.75573192239858907e-6f);
    p = __fmaf_rn(p, r2, -1.98412698412698413e-4f);
    p = __fmaf_rn(p, r2, 8.33333333333333333e-3f);
    p = __fmaf_rn(p, r2, -1.66666666666666667e-1f);
    return __fmaf_rn(__fmul_rn(p, r2), r, r);
}

// ---------------------------------------------------------------------------
// Kernel A: one thread per 16-block: compute the 16 e-values
// e[m] = fl(interp(clip(f0))[m] * fl(1/24000)) (XLA folds div-by-const into
// mul-by-reciprocal) and their serial LTR sum -> g_b0. No e[] array needed.
// ---------------------------------------------------------------------------
__global__ void __launch_bounds__(256) kA(const float* __restrict__ f0) {
    int b = blockIdx.y;
    int p = blockIdx.x * 256 + threadIdx.x;     // 16-block index, < 15360
    const float* f0b = f0 + (size_t)b * TLEN;
    int n0 = p * 16;
    float acc = 0.0f;
#pragma unroll
    for (int r = 0; r < 16; r++) {
        int n = n0 + r;
        float pos = __fmul_rn((float)n + 0.5f, 0.00390625f) - 0.5f;  // exact
        pos = fminf(fmaxf(pos, 0.0f), 959.0f);
        int   i0 = (int)pos;
        int   i1 = min(i0 + 1, 959);
        float w  = pos - (float)i0;              // exact
        float x0 = fminf(fmaxf(__ldg(f0b + i0), 50.0f), 1000.0f);
        float x1 = fminf(fmaxf(__ldg(f0b + i1), 50.0f), 1000.0f);
        float v  = __fadd_rn(__fmul_rn(x0, 1.0f - w), __fmul_rn(x1, w));
        float e  = __fmul_rn(v, (1.0f / 24000.0f));
        acc = __fadd_rn(acc, e);                 // r=0: 0+e0 == e0 exact
    }
    g_b0[(size_t)b * NB0 + p] = acc;
}

// ---------------------------------------------------------------------------
// Kernel B: per batch — blocked radix-16 scan of the 15360 block sums,
// mirroring XLA ReduceWindowRewriter(base_length=16) exactly. Each level:
// incremental LTR running prefix within a 16-block + ONE fadd of the outer
// prefix per element (first block adds nothing). Identical rounding sequence
// to R11, but O(16) instead of O(16^2) adds per block.
// ---------------------------------------------------------------------------
__global__ void __launch_bounds__(256) kB() {
    __shared__ float B1[960], B2[60], SC3[4], SC2[60], SC1[960];
    int b = blockIdx.x;
    const float* b0 = g_b0 + (size_t)b * NB0;
    float* sc0 = g_sc0 + (size_t)b * NB0;
    int tid = threadIdx.x;

    for (int j = tid; j < 960; j += 256) {
        float a = b0[16 * j];
#pragma unroll
        for (int r = 1; r < 16; r++) a = __fadd_rn(a, b0[16 * j + r]);
        B1[j] = a;
    }
    __syncthreads();

    if (tid < 60) {
        float a = B1[16 * tid];
#pragma unroll
        for (int r = 1; r < 16; r++) a = __fadd_rn(a, B1[16 * tid + r]);
        B2[tid] = a;
    }
    __syncthreads();

    if (tid == 0) {
        float B3s[4];
        for (int k = 0; k < 4; k++) {
            int hi = min(16 * k + 16, 60);       // last block: 12 real + 0-pad
            float a = B2[16 * k];
            for (int r = 16 * k + 1; r < hi; r++) a = __fadd_rn(a, B2[r]);
            B3s[k] = a;
        }
        SC3[0] = B3s[0];
        for (int k = 1; k < 4; k++) SC3[k] = __fadd_rn(SC3[k - 1], B3s[k]);
    }
    __syncthreads();

    if (tid < 4) {
        int p = tid;
        int hi = min(16 * p + 16, 60);
        float pre = p ? SC3[p - 1] : 0.0f;
        float acc = B2[16 * p];
        SC2[16 * p] = p ? __fadd_rn(acc, pre) : acc;
        for (int r = 16 * p + 1; r < hi; r++) {
            acc = __fadd_rn(acc, B2[r]);
            SC2[r] = p ? __fadd_rn(acc, pre) : acc;
        }
    }
    __syncthreads();

    if (tid < 60) {
        int p = tid;
        float pre = p ? SC2[p - 1] : 0.0f;
        float acc = B1[16 * p];
        SC1[16 * p] = p ? __fadd_rn(acc, pre) : acc;
#pragma unroll
        for (int r = 1; r < 16; r++) {
            acc = __fadd_rn(acc, B1[16 * p + r]);
            SC1[16 * p + r] = p ? __fadd_rn(acc, pre) : acc;
        }
    }
    __syncthreads();

    for (int p = tid; p < 960; p += 256) {
        float pre = p ? SC1[p - 1] : 0.0f;
        float acc = b0[16 * p];
        sc0[16 * p] = p ? __fadd_rn(acc, pre) : acc;
#pragma unroll
        for (int r = 1; r < 16; r++) {
            acc = __fadd_rn(acc, b0[16 * p + r]);
            sc0[16 * p + r] = p ? __fadd_rn(acc, pre) : acc;
        }
    }
    if (tid == 0) g_maxabs[b] = 0;
}

// ---------------------------------------------------------------------------
// Kernel C (hot): per (batch, 256-sample segment). Recompute e in-kernel from
// 3 smem-cached clipped f0 frames (same interp grid as amps — computed once);
// phase = LTR within the sample's 16-block + one prefix add of SC0[o0-1];
// 32 harmonics: t = fl(fl(2pi*phi)*k), fast sin, amp interp, fma-accumulate.
// Unnormalized harm out; block+atomic max.
// ---------------------------------------------------------------------------
__global__ void __launch_bounds__(256) kC(const float* __restrict__ f0,
                                          const float* __restrict__ ha,
                                          float* __restrict__ out) {
    __shared__ float se[256];
    __shared__ float scp[16];
    __shared__ float f0s[3];
    __shared__ float amps[3][32];
    __shared__ float smax[8];
    int b = blockIdx.y;
    int s = blockIdx.x;
    int i = threadIdx.x;
    int n = s * 256 + i;

    if (i < 3) {
        int t = min(max(s - 1 + i, 0), TLEN - 1);
        f0s[i] = fminf(fmaxf(f0[(size_t)b * TLEN + t], 50.0f), 1000.0f);
    }
    if (i < 16) {
        int o0 = s * 16 + i;
        scp[i] = (o0 == 0) ? 0.0f : g_sc0[(size_t)b * NB0 + o0 - 1];
    }
    if (i < 96) {
        int slot = i >> 5, k = i & 31;
        int t = min(max(s - 1 + slot, 0), TLEN - 1);
        amps[slot][k] = ha[((size_t)(b * NHARM + k)) * TLEN + t];
    }
    __syncthreads();

    // shared interpolation grid (identical for f0 and amps)
    float pos = __fmul_rn((float)n + 0.5f, 0.00390625f) - 0.5f;
    pos = fminf(fmaxf(pos, 0.0f), 959.0f);
    int   i0 = (int)pos;
    int   i1 = min(i0 + 1, 959);
    float w  = pos - (float)i0;
    float omw = 1.0f - w;
    int sl0 = i0 - s + 1;   // slot in {0,1,2}
    int sl1 = i1 - s + 1;

    float v = __fadd_rn(__fmul_rn(f0s[sl0], omw), __fmul_rn(f0s[sl1], w));
    se[i] = __fmul_rn(v, (1.0f / 24000.0f));
    __syncthreads();

    int ob = i >> 4;
    float inner = se[ob << 4];
    for (int r = (ob << 4) + 1; r <= i; r++) inner = __fadd_rn(inner, se[r]);
    float phi = (s == 0 && ob == 0) ? inner : __fadd_rn(inner, scp[ob]);

    float theta = __fmul_rn(6.28318530717958647692f, phi);  // fl(2pi*phi)

    float hsum = 0.0f;
#pragma unroll
    for (int k = 0; k < 32; ++k) {
        float t  = __fmul_rn(theta, (float)(k + 1));
        float sv = fast_sin_pos(t);
        float a  = __fadd_rn(__fmul_rn(amps[sl0][k], omw),
                             __fmul_rn(amps[sl1][k], w));
        hsum = __fmaf_rn(sv, a, hsum);
    }
    out[(size_t)b * NSAMP + n] = hsum;

    float av = fabsf(hsum);
#pragma unroll
    for (int off = 16; off; off >>= 1)
        av = fmaxf(av, __shfl_xor_sync(0xffffffffu, av, off));
    if ((i & 31) == 0) smax[i >> 5] = av;
    __syncthreads();
    if (i == 0) {
        float mv = smax[0];
#pragma unroll
        for (int wv = 1; wv < 8; ++wv) mv = fmaxf(mv, smax[wv]);
        atomicMax(&g_maxabs[b], __float_as_int(mv));
    }
}

// ---------------------------------------------------------------------------
// Kernel D: out /= max(max|harm| + 1e-7, 1), float4-vectorized.
// (Noise path is exactly zero: mel filters collapse below the first bin.)
// ---------------------------------------------------------------------------
__global__ void __launch_bounds__(256) kD(float4* __restrict__ out) {
    int b = blockIdx.y;
    float denom = fmaxf(__fadd_rn(__int_as_float(g_maxabs[b]), 1e-7f), 1.0f);
    size_t idx = (size_t)b * (NSAMP / 4) + blockIdx.x * 256 + threadIdx.x;
    float4 v = out[idx];
    v.x = __fdiv_rn(v.x, denom);
    v.y = __fdiv_rn(v.y, denom);
    v.z = __fdiv_rn(v.z, denom);
    v.w = __fdiv_rn(v.w, denom);
    out[idx] = v;
}

extern "C" void kernel_launch(void* const* d_in, const int* in_sizes, int n_in,
                              void* d_out, int out_size) {
    const float* f0 = (const float*)d_in[0];
    const float* ha = (const float*)d_in[1];
    float* out = (float*)d_out;

    kA<<<dim3(60, BATCH), 256>>>(f0);
    kB<<<BATCH, 256>>>();
    kC<<<dim3(960, BATCH), 256>>>(f0, ha, out);
    kD<<<dim3(240, BATCH), 256>>>((float4*)out);
}

// round 15
// speedup vs baseline: 1.4314x; 1.0936x over previous
#include <cuda_runtime.h>
#include <cuda_bf16.h>
#include <math.h>

// Problem constants (fixed by setup_inputs)
#define BATCH 8
#define TLEN  960
#define NHARM 32
#define NSAMP 245760            // 256 * 960; radix-16 scan levels: 15360/960/60/4
#define NB0   15360             // NSAMP/16

// Scratch (no allocation allowed): 16-block sums + their blocked scan
__device__ float g_b0 [(size_t)BATCH * NB0];
__device__ float g_sc0[(size_t)BATCH * NB0];
__device__ int   g_maxabs[BATCH];

// ---------------------------------------------------------------------------
// Accurate sin AND cos of t in [0, ~2^15), all-fp32 (seeds the rotation).
// pi/2-quadrant magic-number reduction, two-fma Cody-Waite, Taylor polys.
// Abs err ~2e-7.
// ---------------------------------------------------------------------------
__device__ __forceinline__ void sincos_acc(float t, float& so, float& co) {
    const float MAGIC = 12582912.0f;  // 2^23 + 2^22
    float mq = __fmaf_rn(t, 0.63661977236758134308f, MAGIC);
    int   q  = __float_as_int(mq);
    float qf = mq - MAGIC;
    float r  = __fmaf_rn(qf, -1.57079637050628662109f, t);  // t - q*C1
    r = __fmaf_rn(qf, 4.37113882867379188e-8f, r);          // + q*(C1 - pi/2)
    float r2 = __fmul_rn(r, r);
    float sp = __fmaf_rn(2.75573192239859e-6f, r2, -1.98412698412698e-4f);
    sp = __fmaf_rn(sp, r2, 8.33333333333333e-3f);
    sp = __fmaf_rn(sp, r2, -1.66666666666667e-1f);
    float sv = __fmaf_rn(__fmul_rn(sp, r2), r, r);
    float cp = __fmaf_rn(-2.75573192239859e-7f, r2, 2.48015873015873e-5f);
    cp = __fmaf_rn(cp, r2, -1.38888888888889e-3f);
    cp = __fmaf_rn(cp, r2, 4.16666666666667e-2f);
    cp = __fmaf_rn(cp, r2, -0.5f);
    float cv = __fmaf_rn(cp, r2, 1.0f);
    float s = (q & 1) ? cv : sv;
    float c = (q & 1) ? sv : cv;
    s = ((q & 2))       ? -s : s;       // quadrant signs
    c = (((q + 1) & 2)) ? -c : c;
    so = s; co = c;
}

// ---------------------------------------------------------------------------
// Kernel A: one thread per 16-block: compute the 16 e-values
// e[m] = fl(interp(clip(f0))[m] * fl(1/24000)) (XLA folds div-by-const into
// mul-by-reciprocal) and their serial LTR sum -> g_b0.
// ---------------------------------------------------------------------------
__global__ void __launch_bounds__(256) kA(const float* __restrict__ f0) {
    int b = blockIdx.y;
    int p = blockIdx.x * 256 + threadIdx.x;     // 16-block index, < 15360
    const float* f0b = f0 + (size_t)b * TLEN;
    int n0 = p * 16;
    float acc = 0.0f;
#pragma unroll
    for (int r = 0; r < 16; r++) {
        int n = n0 + r;
        float pos = __fmul_rn((float)n + 0.5f, 0.00390625f) - 0.5f;  // exact
        pos = fminf(fmaxf(pos, 0.0f), 959.0f);
        int   i0 = (int)pos;
        int   i1 = min(i0 + 1, 959);
        float w  = pos - (float)i0;              // exact
        float x0 = fminf(fmaxf(__ldg(f0b + i0), 50.0f), 1000.0f);
        float x1 = fminf(fmaxf(__ldg(f0b + i1), 50.0f), 1000.0f);
        float v  = __fadd_rn(__fmul_rn(x0, 1.0f - w), __fmul_rn(x1, w));
        float e  = __fmul_rn(v, (1.0f / 24000.0f));
        acc = __fadd_rn(acc, e);
    }
    g_b0[(size_t)b * NB0 + p] = acc;
}

// ---------------------------------------------------------------------------
// Kernel B: per batch — blocked radix-16 scan of the 15360 block sums,
// mirroring XLA ReduceWindowRewriter(base_length=16) rounding-for-rounding:
// incremental LTR within each 16-block + ONE fadd of the outer prefix per
// element (first block adds nothing; last partial blocks 0-padded exactly).
// ---------------------------------------------------------------------------
__global__ void __launch_bounds__(256) kB() {
    __shared__ float B1[960], B2[60], SC3[4], SC2[60], SC1[960];
    int b = blockIdx.x;
    const float* b0 = g_b0 + (size_t)b * NB0;
    float* sc0 = g_sc0 + (size_t)b * NB0;
    int tid = threadIdx.x;

    for (int j = tid; j < 960; j += 256) {
        float a = b0[16 * j];
#pragma unroll
        for (int r = 1; r < 16; r++) a = __fadd_rn(a, b0[16 * j + r]);
        B1[j] = a;
    }
    __syncthreads();

    if (tid < 60) {
        float a = B1[16 * tid];
#pragma unroll
        for (int r = 1; r < 16; r++) a = __fadd_rn(a, B1[16 * tid + r]);
        B2[tid] = a;
    }
    __syncthreads();

    if (tid == 0) {
        float B3s[4];
        for (int k = 0; k < 4; k++) {
            int hi = min(16 * k + 16, 60);       // last block: 12 real + 0-pad
            float a = B2[16 * k];
            for (int r = 16 * k + 1; r < hi; r++) a = __fadd_rn(a, B2[r]);
            B3s[k] = a;
        }
        SC3[0] = B3s[0];
        for (int k = 1; k < 4; k++) SC3[k] = __fadd_rn(SC3[k - 1], B3s[k]);
    }
    __syncthreads();

    if (tid < 4) {
        int p = tid;
        int hi = min(16 * p + 16, 60);
        float pre = p ? SC3[p - 1] : 0.0f;
        float acc = B2[16 * p];
        SC2[16 * p] = p ? __fadd_rn(acc, pre) : acc;
        for (int r = 16 * p + 1; r < hi; r++) {
            acc = __fadd_rn(acc, B2[r]);
            SC2[r] = p ? __fadd_rn(acc, pre) : acc;
        }
    }
    __syncthreads();

    if (tid < 60) {
        int p = tid;
        float pre = p ? SC2[p - 1] : 0.0f;
        float acc = B1[16 * p];
        SC1[16 * p] = p ? __fadd_rn(acc, pre) : acc;
#pragma unroll
        for (int r = 1; r < 16; r++) {
            acc = __fadd_rn(acc, B1[16 * p + r]);
            SC1[16 * p + r] = p ? __fadd_rn(acc, pre) : acc;
        }
    }
    __syncthreads();

    for (int p = tid; p < 960; p += 256) {
        float pre = p ? SC1[p - 1] : 0.0f;
        float acc = b0[16 * p];
        sc0[16 * p] = p ? __fadd_rn(acc, pre) : acc;
#pragma unroll
        for (int r = 1; r < 16; r++) {
            acc = __fadd_rn(acc, b0[16 * p + r]);
            sc0[16 * p + r] = p ? __fadd_rn(acc, pre) : acc;
        }
    }
    if (tid == 0) g_maxabs[b] = 0;
}

// ---------------------------------------------------------------------------
// Kernel C (hot): per (batch, 256-sample segment).
// Phase: recompute e from 3 smem f0 frames; LTR within 16-block + one prefix
// add of SC0 (exact XLA order). Harmonics: rotation recurrence for
// (sin k*theta, cos k*theta); the reference's argument is t = fl(theta*k) =
// k*theta - d with d = fma(theta,k,-t) EXACT, so
//   sin(t) = sin(k*theta - d) ~= (sk - ck*d) * (1 - d^2/2)   [err ck*d^3/3]
// ~13 FMA-class ops per harmonic.
// ---------------------------------------------------------------------------
__global__ void __launch_bounds__(256) kC(const float* __restrict__ f0,
                                          const float* __restrict__ ha,
                                          float* __restrict__ out) {
    __shared__ float se[256];
    __shared__ float scp[16];
    __shared__ float f0s[3];
    __shared__ float amps[3][32];
    __shared__ float damp[2][32];
    __shared__ float smax[8];
    int b = blockIdx.y;
    int s = blockIdx.x;
    int i = threadIdx.x;
    int n = s * 256 + i;

    if (i < 3) {
        int t = min(max(s - 1 + i, 0), TLEN - 1);
        f0s[i] = fminf(fmaxf(f0[(size_t)b * TLEN + t], 50.0f), 1000.0f);
    }
    if (i < 16) {
        int o0 = s * 16 + i;
        scp[i] = (o0 == 0) ? 0.0f : g_sc0[(size_t)b * NB0 + o0 - 1];
    }
    if (i < 96) {
        int slot = i >> 5, k = i & 31;
        int t = min(max(s - 1 + slot, 0), TLEN - 1);
        amps[slot][k] = ha[((size_t)(b * NHARM + k)) * TLEN + t];
    }
    __syncthreads();

    // interpolation grid (shared by f0 and amps)
    float pos = __fmul_rn((float)n + 0.5f, 0.00390625f) - 0.5f;
    pos = fminf(fmaxf(pos, 0.0f), 959.0f);
    int   i0 = (int)pos;
    float w  = pos - (float)i0;
    float omw = 1.0f - w;
    int sl0 = i0 - s + 1;   // 0 or 1

    float v = __fadd_rn(__fmul_rn(f0s[sl0], omw), __fmul_rn(f0s[sl0 + 1], w));
    se[i] = __fmul_rn(v, (1.0f / 24000.0f));
    if (i < 64) {
        int slot = i >> 5, k = i & 31;   // slot 0: amps1-amps0; slot 1: amps2-amps1
        damp[slot][k] = amps[slot + 1][k] - amps[slot][k];  // edge frames equal -> 0
    }
    __syncthreads();

    int ob = i >> 4;
    float inner = se[ob << 4];
    for (int r = (ob << 4) + 1; r <= i; r++) inner = __fadd_rn(inner, se[r]);
    float phi = (s == 0 && ob == 0) ? inner : __fadd_rn(inner, scp[ob]);

    float theta = __fmul_rn(6.28318530717958647692f, phi);  // fl(2pi*phi)

    float s1, c1;
    sincos_acc(theta, s1, c1);
    float sk = s1, ck = c1;   // sin/cos of k*theta (real-multiple angle)

    const float* arow = amps[sl0];
    const float* drow = damp[sl0];

    float hsum = 0.0f;
#pragma unroll
    for (int k = 0; k < 32; ++k) {
        float kf = (float)(k + 1);
        float t  = __fmul_rn(theta, kf);                 // reference's argument
        float d  = __fmaf_rn(theta, kf, -t);             // EXACT: theta*k - t
        float dd = __fmul_rn(d, d);
        float sv = __fmaf_rn(ck, -d, sk);                // sk - ck*d  (sign fix)
        float hdd = __fmul_rn(dd, -0.5f);
        sv = __fmaf_rn(sv, hdd, sv);                     // *(1 - d^2/2)
        float a  = __fmaf_rn(drow[k], w, arow[k]);
        hsum = __fmaf_rn(sv, a, hsum);
        // rotate (s,c) by theta
        float ns = __fmaf_rn(sk, c1, __fmul_rn(ck, s1));
        ck = __fmaf_rn(ck, c1, -__fmul_rn(sk, s1));
        sk = ns;
    }
    out[(size_t)b * NSAMP + n] = hsum;

    float av = fabsf(hsum);
#pragma unroll
    for (int off = 16; off; off >>= 1)
        av = fmaxf(av, __shfl_xor_sync(0xffffffffu, av, off));
    if ((i & 31) == 0) smax[i >> 5] = av;
    __syncthreads();
    if (i == 0) {
        float mv = smax[0];
#pragma unroll
        for (int wv = 1; wv < 8; ++wv) mv = fmaxf(mv, smax[wv]);
        atomicMax(&g_maxabs[b], __float_as_int(mv));
    }
}

// ---------------------------------------------------------------------------
// Kernel D: out *= rcp(max(max|harm| + 1e-7, 1)); 4 float4 per thread for MLP.
// (Noise path is exactly zero: mel filters collapse below the first bin.)
// ---------------------------------------------------------------------------
__global__ void __launch_bounds__(256) kD(float4* __restrict__ out) {
    int b = blockIdx.y;
    float denom = fmaxf(__fadd_rn(__int_as_float(g_maxabs[b]), 1e-7f), 1.0f);
    float inv = __frcp_rn(denom);
    size_t base = (size_t)b * (NSAMP / 4) + blockIdx.x * 1024 + threadIdx.x;
    float4 v0 = out[base];
    float4 v1 = out[base + 256];
    float4 v2 = out[base + 512];
    float4 v3 = out[base + 768];
    v0.x *= inv; v0.y *= inv; v0.z *= inv; v0.w *= inv;
    v1.x *= inv; v1.y *= inv; v1.z *= inv; v1.w *= inv;
    v2.x *= inv; v2.y *= inv; v2.z *= inv; v2.w *= inv;
    v3.x *= inv; v3.y *= inv; v3.z *= inv; v3.w *= inv;
    out[base]       = v0;
    out[base + 256] = v1;
    out[base + 512] = v2;
    out[base + 768] = v3;
}

extern "C" void kernel_launch(void* const* d_in, const int* in_sizes, int n_in,
                              void* d_out, int out_size) {
    const float* f0 = (const float*)d_in[0];
    const float* ha = (const float*)d_in[1];
    float* out = (float*)d_out;

    kA<<<dim3(60, BATCH), 256>>>(f0);
    kB<<<BATCH, 256>>>();
    kC<<<dim3(960, BATCH), 256>>>(f0, ha, out);
    kD<<<dim3(60, BATCH), 256>>>((float4*)out);
}

// round 16
// speedup vs baseline: 1.5348x; 1.0722x over previous
#include <cuda_runtime.h>
#include <cuda_bf16.h>
#include <math.h>

// Problem constants (fixed by setup_inputs)
#define BATCH 8
#define TLEN  960
#define NHARM 32
#define NSAMP 245760            // 256 * 960; radix-16 scan levels: 15360/960/60/4
#define NB0   15360             // NSAMP/16

typedef unsigned long long u64;

// Scratch (no allocation allowed): 16-block sums + their blocked scan
__device__ float g_b0 [(size_t)BATCH * NB0];
__device__ float g_sc0[(size_t)BATCH * NB0];
__device__ int   g_maxabs[BATCH];

// ---------------- packed f32x2 helpers (Blackwell FFMA2 path) --------------
__device__ __forceinline__ u64 f2_pack(float lo, float hi) {
    u64 r; asm("mov.b64 %0, {%1, %2};" : "=l"(r) : "f"(lo), "f"(hi)); return r;
}
__device__ __forceinline__ void f2_unpack(u64 v, float& lo, float& hi) {
    asm("mov.b64 {%0, %1}, %2;" : "=f"(lo), "=f"(hi) : "l"(v));
}
__device__ __forceinline__ u64 f2_fma(u64 a, u64 b, u64 c) {
    u64 r; asm("fma.rn.f32x2 %0, %1, %2, %3;" : "=l"(r) : "l"(a), "l"(b), "l"(c));
    return r;
}
__device__ __forceinline__ u64 f2_mul(u64 a, u64 b) {
    u64 r; asm("mul.rn.f32x2 %0, %1, %2;" : "=l"(r) : "l"(a), "l"(b)); return r;
}
__device__ __forceinline__ u64 f2_neg(u64 a) { return a ^ 0x8000000080000000ULL; }

// ---------------------------------------------------------------------------
// Accurate sin AND cos of t in [0, ~2^20), all-fp32 (seeds the rotation).
// pi/2-quadrant magic-number reduction, two-fma Cody-Waite, Taylor polys.
// Abs err ~2e-7.
// ---------------------------------------------------------------------------
__device__ __forceinline__ void sincos_acc(float t, float& so, float& co) {
    const float MAGIC = 12582912.0f;  // 2^23 + 2^22
    float mq = __fmaf_rn(t, 0.63661977236758134308f, MAGIC);
    int   q  = __float_as_int(mq);
    float qf = mq - MAGIC;
    float r  = __fmaf_rn(qf, -1.57079637050628662109f, t);  // t - q*C1
    r = __fmaf_rn(qf, 4.37113882867379188e-8f, r);          // + q*(C1 - pi/2)
    float r2 = __fmul_rn(r, r);
    float sp = __fmaf_rn(2.75573192239859e-6f, r2, -1.98412698412698e-4f);
    sp = __fmaf_rn(sp, r2, 8.33333333333333e-3f);
    sp = __fmaf_rn(sp, r2, -1.66666666666667e-1f);
    float sv = __fmaf_rn(__fmul_rn(sp, r2), r, r);
    float cp = __fmaf_rn(-2.75573192239859e-7f, r2, 2.48015873015873e-5f);
    cp = __fmaf_rn(cp, r2, -1.38888888888889e-3f);
    cp = __fmaf_rn(cp, r2, 4.16666666666667e-2f);
    cp = __fmaf_rn(cp, r2, -0.5f);
    float cv = __fmaf_rn(cp, r2, 1.0f);
    float s = (q & 1) ? cv : sv;
    float c = (q & 1) ? sv : cv;
    s = ((q & 2))       ? -s : s;       // quadrant signs
    c = (((q + 1) & 2)) ? -c : c;
    so = s; co = c;
}

// ---------------------------------------------------------------------------
// Kernel A: one thread per 16-block: e[m] = fl(interp(clip(f0))[m]*fl(1/24000))
// (XLA folds div-by-const into mul-by-reciprocal); serial LTR 16-sum -> g_b0.
// ---------------------------------------------------------------------------
__global__ void __launch_bounds__(256) kA(const float* __restrict__ f0) {
    int b = blockIdx.y;
    int p = blockIdx.x * 256 + threadIdx.x;     // 16-block index, < 15360
    const float* f0b = f0 + (size_t)b * TLEN;
    int n0 = p * 16;
    float acc = 0.0f;
#pragma unroll
    for (int r = 0; r < 16; r++) {
        int n = n0 + r;
        float pos = __fmul_rn((float)n + 0.5f, 0.00390625f) - 0.5f;  // exact
        pos = fminf(fmaxf(pos, 0.0f), 959.0f);
        int   i0 = (int)pos;
        int   i1 = min(i0 + 1, 959);
        float w  = pos - (float)i0;              // exact
        float x0 = fminf(fmaxf(__ldg(f0b + i0), 50.0f), 1000.0f);
        float x1 = fminf(fmaxf(__ldg(f0b + i1), 50.0f), 1000.0f);
        float v  = __fadd_rn(__fmul_rn(x0, 1.0f - w), __fmul_rn(x1, w));
        float e  = __fmul_rn(v, (1.0f / 24000.0f));
        acc = __fadd_rn(acc, e);
    }
    g_b0[(size_t)b * NB0 + p] = acc;
}

// ---------------------------------------------------------------------------
// Kernel B: per batch — blocked radix-16 scan of the 15360 block sums,
// mirroring XLA ReduceWindowRewriter(base_length=16) rounding-for-rounding.
// ---------------------------------------------------------------------------
__global__ void __launch_bounds__(256) kB() {
    __shared__ float B1[960], B2[60], SC3[4], SC2[60], SC1[960];
    int b = blockIdx.x;
    const float* b0 = g_b0 + (size_t)b * NB0;
    float* sc0 = g_sc0 + (size_t)b * NB0;
    int tid = threadIdx.x;

    for (int j = tid; j < 960; j += 256) {
        float a = b0[16 * j];
#pragma unroll
        for (int r = 1; r < 16; r++) a = __fadd_rn(a, b0[16 * j + r]);
        B1[j] = a;
    }
    __syncthreads();

    if (tid < 60) {
        float a = B1[16 * tid];
#pragma unroll
        for (int r = 1; r < 16; r++) a = __fadd_rn(a, B1[16 * tid + r]);
        B2[tid] = a;
    }
    __syncthreads();

    if (tid == 0) {
        float B3s[4];
        for (int k = 0; k < 4; k++) {
            int hi = min(16 * k + 16, 60);       // last block: 12 real + 0-pad
            float a = B2[16 * k];
            for (int r = 16 * k + 1; r < hi; r++) a = __fadd_rn(a, B2[r]);
            B3s[k] = a;
        }
        SC3[0] = B3s[0];
        for (int k = 1; k < 4; k++) SC3[k] = __fadd_rn(SC3[k - 1], B3s[k]);
    }
    __syncthreads();

    if (tid < 4) {
        int p = tid;
        int hi = min(16 * p + 16, 60);
        float pre = p ? SC3[p - 1] : 0.0f;
        float acc = B2[16 * p];
        SC2[16 * p] = p ? __fadd_rn(acc, pre) : acc;
        for (int r = 16 * p + 1; r < hi; r++) {
            acc = __fadd_rn(acc, B2[r]);
            SC2[r] = p ? __fadd_rn(acc, pre) : acc;
        }
    }
    __syncthreads();

    if (tid < 60) {
        int p = tid;
        float pre = p ? SC2[p - 1] : 0.0f;
        float acc = B1[16 * p];
        SC1[16 * p] = p ? __fadd_rn(acc, pre) : acc;
#pragma unroll
        for (int r = 1; r < 16; r++) {
            acc = __fadd_rn(acc, B1[16 * p + r]);
            SC1[16 * p + r] = p ? __fadd_rn(acc, pre) : acc;
        }
    }
    __syncthreads();

    for (int p = tid; p < 960; p += 256) {
        float pre = p ? SC1[p - 1] : 0.0f;
        float acc = b0[16 * p];
        sc0[16 * p] = p ? __fadd_rn(acc, pre) : acc;
#pragma unroll
        for (int r = 1; r < 16; r++) {
            acc = __fadd_rn(acc, b0[16 * p + r]);
            sc0[16 * p + r] = p ? __fadd_rn(acc, pre) : acc;
        }
    }
    if (tid == 0) g_maxabs[b] = 0;
}

// ---------------------------------------------------------------------------
// Kernel C (hot): per (batch, 256-sample segment).
// Phase as before (exact XLA radix-16 order). Harmonics in PACKED f32x2
// pairs: lane0 = odd k, lane1 = even k, rotation by 2*theta per step.
// Per lane: t = fl(theta*k) (reference's argument), d = fma residual (exact),
// sin(t) ~= (sk - ck*d)*(1 - d^2/2). 12 packed FMA-issues per pair.
// ---------------------------------------------------------------------------
__global__ void __launch_bounds__(256) kC(const float* __restrict__ f0,
                                          const float* __restrict__ ha,
                                          float* __restrict__ out) {
    __shared__ float se[256];
    __shared__ float scp[16];
    __shared__ float f0s[3];
    __shared__ __align__(8) float amps[3][32];
    __shared__ __align__(8) float damp[2][32];
    __shared__ float smax[8];
    int b = blockIdx.y;
    int s = blockIdx.x;
    int i = threadIdx.x;
    int n = s * 256 + i;

    if (i < 3) {
        int t = min(max(s - 1 + i, 0), TLEN - 1);
        f0s[i] = fminf(fmaxf(f0[(size_t)b * TLEN + t], 50.0f), 1000.0f);
    }
    if (i < 16) {
        int o0 = s * 16 + i;
        scp[i] = (o0 == 0) ? 0.0f : g_sc0[(size_t)b * NB0 + o0 - 1];
    }
    if (i < 96) {
        int slot = i >> 5, k = i & 31;
        int t = min(max(s - 1 + slot, 0), TLEN - 1);
        amps[slot][k] = ha[((size_t)(b * NHARM + k)) * TLEN + t];
    }
    __syncthreads();

    // interpolation grid (shared by f0 and amps)
    float pos = __fmul_rn((float)n + 0.5f, 0.00390625f) - 0.5f;
    pos = fminf(fmaxf(pos, 0.0f), 959.0f);
    int   i0 = (int)pos;
    float w  = pos - (float)i0;
    float omw = 1.0f - w;
    int sl0 = i0 - s + 1;   // 0 or 1

    float v = __fadd_rn(__fmul_rn(f0s[sl0], omw), __fmul_rn(f0s[sl0 + 1], w));
    se[i] = __fmul_rn(v, (1.0f / 24000.0f));
    if (i < 64) {
        int slot = i >> 5, k = i & 31;
        damp[slot][k] = amps[slot + 1][k] - amps[slot][k];  // edge frames -> 0
    }
    __syncthreads();

    int ob = i >> 4;
    float inner = se[ob << 4];
    for (int r = (ob << 4) + 1; r <= i; r++) inner = __fadd_rn(inner, se[r]);
    float phi = (s == 0 && ob == 0) ? inner : __fadd_rn(inner, scp[ob]);

    float theta = __fmul_rn(6.28318530717958647692f, phi);  // fl(2pi*phi)

    // seed: (sin,cos)(theta) accurate; double-angle for 2*theta
    float s1, c1;
    sincos_acc(theta, s1, c1);
    float s2 = __fmul_rn(__fmul_rn(2.0f, s1), c1);          // sin 2theta
    float c2 = __fmaf_rn(__fmul_rn(-2.0f, s1), s1, 1.0f);   // cos 2theta

    u64 theta2 = f2_pack(theta, theta);
    u64 w2     = f2_pack(w, w);
    u64 sk2    = f2_pack(s1, s2);        // lanes: k=1, k=2
    u64 ck2    = f2_pack(c1, c2);
    u64 c2v    = f2_pack(c2, c2);        // rotation by 2theta
    u64 s2v    = f2_pack(s2, s2);
    u64 ns2v   = f2_neg(s2v);
    const u64 NEGHALF2 = 0xBF000000BF000000ULL;  // (-0.5f, -0.5f)

    const u64* ar2 = (const u64*)amps[sl0];
    const u64* dr2 = (const u64*)damp[sl0];

    u64 hsum2 = 0ULL;   // (0.0f, 0.0f)
#pragma unroll
    for (int p = 0; p < 16; ++p) {
        u64 kk2 = f2_pack((float)(2 * p + 1), (float)(2 * p + 2));
        u64 t2  = f2_mul(theta2, kk2);                 // reference's arguments
        u64 d2  = f2_fma(theta2, kk2, f2_neg(t2));     // exact residuals
        u64 sv2 = f2_fma(ck2, f2_neg(d2), sk2);        // sk - ck*d
        u64 dd2 = f2_mul(d2, d2);
        u64 hdd2 = f2_mul(dd2, NEGHALF2);
        sv2 = f2_fma(sv2, hdd2, sv2);                  // *(1 - d^2/2)
        u64 a2 = f2_fma(dr2[p], w2, ar2[p]);
        hsum2 = f2_fma(sv2, a2, hsum2);
        // rotate (sk,ck) by 2theta
        u64 ns = f2_fma(sk2, c2v, f2_mul(ck2, s2v));
        ck2 = f2_fma(ck2, c2v, f2_mul(sk2, ns2v));
        sk2 = ns;
    }
    float h0, h1;
    f2_unpack(hsum2, h0, h1);
    float hsum = __fadd_rn(h0, h1);
    out[(size_t)b * NSAMP + n] = hsum;

    float av = fabsf(hsum);
#pragma unroll
    for (int off = 16; off; off >>= 1)
        av = fmaxf(av, __shfl_xor_sync(0xffffffffu, av, off));
    if ((i & 31) == 0) smax[i >> 5] = av;
    __syncthreads();
    if (i == 0) {
        float mv = smax[0];
#pragma unroll
        for (int wv = 1; wv < 8; ++wv) mv = fmaxf(mv, smax[wv]);
        atomicMax(&g_maxabs[b], __float_as_int(mv));
    }
}

// ---------------------------------------------------------------------------
// Kernel D: out *= rcp(max(max|harm| + 1e-7, 1)); one float4 per thread
// (240x8 grid — best measured shape). Noise path is exactly zero.
// ---------------------------------------------------------------------------
__global__ void __launch_bounds__(256) kD(float4* __restrict__ out) {
    int b = blockIdx.y;
    float denom = fmaxf(__fadd_rn(__int_as_float(g_maxabs[b]), 1e-7f), 1.0f);
    float inv = __frcp_rn(denom);
    size_t idx = (size_t)b * (NSAMP / 4) + blockIdx.x * 256 + threadIdx.x;
    float4 v = out[idx];
    v.x *= inv; v.y *= inv; v.z *= inv; v.w *= inv;
    out[idx] = v;
}

extern "C" void kernel_launch(void* const* d_in, const int* in_sizes, int n_in,
                              void* d_out, int out_size) {
    const float* f0 = (const float*)d_in[0];
    const float* ha = (const float*)d_in[1];
    float* out = (float*)d_out;

    kA<<<dim3(60, BATCH), 256>>>(f0);
    kB<<<BATCH, 256>>>();
    kC<<<dim3(960, BATCH), 256>>>(f0, ha, out);
    kD<<<dim3(240, BATCH), 256>>>((float4*)out);
}

// round 17
// speedup vs baseline: 1.6865x; 1.0988x over previous
#include <cuda_runtime.h>
#include <cuda_bf16.h>
#include <math.h>

// Problem constants (fixed by setup_inputs)
#define BATCH 8
#define TLEN  960
#define NHARM 32
#define NSAMP 245760            // 256 * 960; radix-16 scan levels: 15360/960/60/4
#define NB0   15360             // NSAMP/16

typedef unsigned long long u64;

// Scratch (no allocation allowed): 16-block sums + their blocked scan
__device__ float g_b0 [(size_t)BATCH * NB0];
__device__ float g_sc0[(size_t)BATCH * NB0];
__device__ int   g_maxabs[BATCH];

// ---------------- packed f32x2 helpers (Blackwell FFMA2 path) --------------
__device__ __forceinline__ u64 f2_pack(float lo, float hi) {
    u64 r; asm("mov.b64 %0, {%1, %2};" : "=l"(r) : "f"(lo), "f"(hi)); return r;
}
__device__ __forceinline__ void f2_unpack(u64 v, float& lo, float& hi) {
    asm("mov.b64 {%0, %1}, %2;" : "=f"(lo), "=f"(hi) : "l"(v));
}
__device__ __forceinline__ u64 f2_fma(u64 a, u64 b, u64 c) {
    u64 r; asm("fma.rn.f32x2 %0, %1, %2, %3;" : "=l"(r) : "l"(a), "l"(b), "l"(c));
    return r;
}
__device__ __forceinline__ u64 f2_mul(u64 a, u64 b) {
    u64 r; asm("mul.rn.f32x2 %0, %1, %2;" : "=l"(r) : "l"(a), "l"(b)); return r;
}
__device__ __forceinline__ u64 f2_add(u64 a, u64 b) {
    u64 r; asm("add.rn.f32x2 %0, %1, %2;" : "=l"(r) : "l"(a), "l"(b)); return r;
}
__device__ __forceinline__ u64 f2_neg(u64 a) { return a ^ 0x8000000080000000ULL; }

// ---------------------------------------------------------------------------
// Accurate sin AND cos of t in [0, ~2^20), all-fp32 (seeds the rotation).
// pi/2-quadrant magic-number reduction, two-fma Cody-Waite, Taylor polys.
// Abs err ~2e-7.
// ---------------------------------------------------------------------------
__device__ __forceinline__ void sincos_acc(float t, float& so, float& co) {
    const float MAGIC = 12582912.0f;  // 2^23 + 2^22
    float mq = __fmaf_rn(t, 0.63661977236758134308f, MAGIC);
    int   q  = __float_as_int(mq);
    float qf = mq - MAGIC;
    float r  = __fmaf_rn(qf, -1.57079637050628662109f, t);  // t - q*C1
    r = __fmaf_rn(qf, 4.37113882867379188e-8f, r);          // + q*(C1 - pi/2)
    float r2 = __fmul_rn(r, r);
    float sp = __fmaf_rn(2.75573192239859e-6f, r2, -1.98412698412698e-4f);
    sp = __fmaf_rn(sp, r2, 8.33333333333333e-3f);
    sp = __fmaf_rn(sp, r2, -1.66666666666667e-1f);
    float sv = __fmaf_rn(__fmul_rn(sp, r2), r, r);
    float cp = __fmaf_rn(-2.75573192239859e-7f, r2, 2.48015873015873e-5f);
    cp = __fmaf_rn(cp, r2, -1.38888888888889e-3f);
    cp = __fmaf_rn(cp, r2, 4.16666666666667e-2f);
    cp = __fmaf_rn(cp, r2, -0.5f);
    float cv = __fmaf_rn(cp, r2, 1.0f);
    float s = (q & 1) ? cv : sv;
    float c = (q & 1) ? sv : cv;
    s = ((q & 2))       ? -s : s;       // quadrant signs
    c = (((q + 1) & 2)) ? -c : c;
    so = s; co = c;
}

// ---------------------------------------------------------------------------
// Kernel A: one thread per 16-block: e[m] = fl(interp(clip(f0))[m]*fl(1/24000))
// (XLA folds div-by-const into mul-by-reciprocal); serial LTR 16-sum -> g_b0.
// ---------------------------------------------------------------------------
__global__ void __launch_bounds__(256) kA(const float* __restrict__ f0) {
    int b = blockIdx.y;
    int p = blockIdx.x * 256 + threadIdx.x;     // 16-block index, < 15360
    const float* f0b = f0 + (size_t)b * TLEN;
    int n0 = p * 16;
    float acc = 0.0f;
#pragma unroll
    for (int r = 0; r < 16; r++) {
        int n = n0 + r;
        float pos = __fmul_rn((float)n + 0.5f, 0.00390625f) - 0.5f;  // exact
        pos = fminf(fmaxf(pos, 0.0f), 959.0f);
        int   i0 = (int)pos;
        int   i1 = min(i0 + 1, 959);
        float w  = pos - (float)i0;              // exact
        float x0 = fminf(fmaxf(__ldg(f0b + i0), 50.0f), 1000.0f);
        float x1 = fminf(fmaxf(__ldg(f0b + i1), 50.0f), 1000.0f);
        float v  = __fadd_rn(__fmul_rn(x0, 1.0f - w), __fmul_rn(x1, w));
        float e  = __fmul_rn(v, (1.0f / 24000.0f));
        acc = __fadd_rn(acc, e);
    }
    g_b0[(size_t)b * NB0 + p] = acc;
}

// ---------------------------------------------------------------------------
// Kernel B: per batch — blocked radix-16 scan of the 15360 block sums,
// mirroring XLA ReduceWindowRewriter(base_length=16) rounding-for-rounding.
// ---------------------------------------------------------------------------
__global__ void __launch_bounds__(256) kB() {
    __shared__ float B1[960], B2[60], SC3[4], SC2[60], SC1[960];
    int b = blockIdx.x;
    const float* b0 = g_b0 + (size_t)b * NB0;
    float* sc0 = g_sc0 + (size_t)b * NB0;
    int tid = threadIdx.x;

    for (int j = tid; j < 960; j += 256) {
        float a = b0[16 * j];
#pragma unroll
        for (int r = 1; r < 16; r++) a = __fadd_rn(a, b0[16 * j + r]);
        B1[j] = a;
    }
    __syncthreads();

    if (tid < 60) {
        float a = B1[16 * tid];
#pragma unroll
        for (int r = 1; r < 16; r++) a = __fadd_rn(a, B1[16 * tid + r]);
        B2[tid] = a;
    }
    __syncthreads();

    if (tid == 0) {
        float B3s[4];
        for (int k = 0; k < 4; k++) {
            int hi = min(16 * k + 16, 60);       // last block: 12 real + 0-pad
            float a = B2[16 * k];
            for (int r = 16 * k + 1; r < hi; r++) a = __fadd_rn(a, B2[r]);
            B3s[k] = a;
        }
        SC3[0] = B3s[0];
        for (int k = 1; k < 4; k++) SC3[k] = __fadd_rn(SC3[k - 1], B3s[k]);
    }
    __syncthreads();

    if (tid < 4) {
        int p = tid;
        int hi = min(16 * p + 16, 60);
        float pre = p ? SC3[p - 1] : 0.0f;
        float acc = B2[16 * p];
        SC2[16 * p] = p ? __fadd_rn(acc, pre) : acc;
        for (int r = 16 * p + 1; r < hi; r++) {
            acc = __fadd_rn(acc, B2[r]);
            SC2[r] = p ? __fadd_rn(acc, pre) : acc;
        }
    }
    __syncthreads();

    if (tid < 60) {
        int p = tid;
        float pre = p ? SC2[p - 1] : 0.0f;
        float acc = B1[16 * p];
        SC1[16 * p] = p ? __fadd_rn(acc, pre) : acc;
#pragma unroll
        for (int r = 1; r < 16; r++) {
            acc = __fadd_rn(acc, B1[16 * p + r]);
            SC1[16 * p + r] = p ? __fadd_rn(acc, pre) : acc;
        }
    }
    __syncthreads();

    for (int p = tid; p < 960; p += 256) {
        float pre = p ? SC1[p - 1] : 0.0f;
        float acc = b0[16 * p];
        sc0[16 * p] = p ? __fadd_rn(acc, pre) : acc;
#pragma unroll
        for (int r = 1; r < 16; r++) {
            acc = __fadd_rn(acc, b0[16 * p + r]);
            sc0[16 * p + r] = p ? __fadd_rn(acc, pre) : acc;
        }
    }
    if (tid == 0) g_maxabs[b] = 0;
}

// ---------------------------------------------------------------------------
// Kernel C (hot): per (batch, 256-sample segment).
// Phase: exact XLA radix-16 order. Harmonics in PACKED f32x2 pairs
// (lane0 = odd k, lane1 = even k, rotation by 2theta/step). Reference's
// argument t = fl(theta*k) = k*theta - d; the sign-absorbed exact residual
// d2n = fma(-theta, k, t) = -d gives sin(t) ~= sk + ck*d2n (first order;
// dropped d^2/2 term contributes ~5e-5 rel, budget 1e-3).
// 10 packed FMA-issues per pair (5 per harmonic).
// ---------------------------------------------------------------------------
__global__ void __launch_bounds__(256) kC(const float* __restrict__ f0,
                                          const float* __restrict__ ha,
                                          float* __restrict__ out) {
    __shared__ float se[256];
    __shared__ float scp[16];
    __shared__ float f0s[3];
    __shared__ __align__(8) float amps[3][32];
    __shared__ __align__(8) float damp[2][32];
    __shared__ float smax[8];
    int b = blockIdx.y;
    int s = blockIdx.x;
    int i = threadIdx.x;
    int n = s * 256 + i;

    if (i < 3) {
        int t = min(max(s - 1 + i, 0), TLEN - 1);
        f0s[i] = fminf(fmaxf(f0[(size_t)b * TLEN + t], 50.0f), 1000.0f);
    }
    if (i < 16) {
        int o0 = s * 16 + i;
        scp[i] = (o0 == 0) ? 0.0f : g_sc0[(size_t)b * NB0 + o0 - 1];
    }
    if (i < 96) {
        int slot = i >> 5, k = i & 31;
        int t = min(max(s - 1 + slot, 0), TLEN - 1);
        amps[slot][k] = ha[((size_t)(b * NHARM + k)) * TLEN + t];
    }
    __syncthreads();

    // interpolation grid (shared by f0 and amps)
    float pos = __fmul_rn((float)n + 0.5f, 0.00390625f) - 0.5f;
    pos = fminf(fmaxf(pos, 0.0f), 959.0f);
    int   i0 = (int)pos;
    float w  = pos - (float)i0;
    float omw = 1.0f - w;
    int sl0 = i0 - s + 1;   // 0 or 1

    float v = __fadd_rn(__fmul_rn(f0s[sl0], omw), __fmul_rn(f0s[sl0 + 1], w));
    se[i] = __fmul_rn(v, (1.0f / 24000.0f));
    if (i < 64) {
        int slot = i >> 5, k = i & 31;
        damp[slot][k] = amps[slot + 1][k] - amps[slot][k];  // edge frames -> 0
    }
    __syncthreads();

    int ob = i >> 4;
    float inner = se[ob << 4];
    for (int r = (ob << 4) + 1; r <= i; r++) inner = __fadd_rn(inner, se[r]);
    float phi = (s == 0 && ob == 0) ? inner : __fadd_rn(inner, scp[ob]);

    float theta = __fmul_rn(6.28318530717958647692f, phi);  // fl(2pi*phi)

    // seed: (sin,cos)(theta) accurate; double-angle for 2*theta
    float s1, c1;
    sincos_acc(theta, s1, c1);
    float s2 = __fmul_rn(__fmul_rn(2.0f, s1), c1);          // sin 2theta
    float c2 = __fmaf_rn(__fmul_rn(-2.0f, s1), s1, 1.0f);   // cos 2theta

    u64 theta2  = f2_pack(theta, theta);
    u64 ntheta2 = f2_neg(theta2);
    u64 w2      = f2_pack(w, w);
    u64 sk2     = f2_pack(s1, s2);        // lanes: k=1, k=2
    u64 ck2     = f2_pack(c1, c2);
    u64 c2v     = f2_pack(c2, c2);        // rotation by 2theta
    u64 s2v     = f2_pack(s2, s2);
    u64 ns2v    = f2_neg(s2v);
    u64 kk2     = f2_pack(1.0f, 2.0f);
    const u64 TWO2 = 0x4000000040000000ULL;   // (2.0f, 2.0f)

    const u64* ar2 = (const u64*)amps[sl0];
    const u64* dr2 = (const u64*)damp[sl0];

    u64 hsum2 = 0ULL;   // (0.0f, 0.0f)
#pragma unroll
    for (int p = 0; p < 16; ++p) {
        u64 t2  = f2_mul(theta2, kk2);             // reference's arguments
        u64 d2n = f2_fma(ntheta2, kk2, t2);        // EXACT: t - theta*k = -d
        u64 sv2 = f2_fma(ck2, d2n, sk2);           // sk - ck*d  (1st order)
        u64 a2  = f2_fma(dr2[p], w2, ar2[p]);
        hsum2 = f2_fma(sv2, a2, hsum2);
        // rotate (sk,ck) by 2theta; advance kk
        u64 ns = f2_fma(sk2, c2v, f2_mul(ck2, s2v));
        ck2 = f2_fma(ck2, c2v, f2_mul(sk2, ns2v));
        sk2 = ns;
        kk2 = f2_add(kk2, TWO2);                   // exact small ints
    }
    float h0, h1;
    f2_unpack(hsum2, h0, h1);
    float hsum = __fadd_rn(h0, h1);
    out[(size_t)b * NSAMP + n] = hsum;

    float av = fabsf(hsum);
#pragma unroll
    for (int off = 16; off; off >>= 1)
        av = fmaxf(av, __shfl_xor_sync(0xffffffffu, av, off));
    if ((i & 31) == 0) smax[i >> 5] = av;
    __syncthreads();
    if (i == 0) {
        float mv = smax[0];
#pragma unroll
        for (int wv = 1; wv < 8; ++wv) mv = fmaxf(mv, smax[wv]);
        atomicMax(&g_maxabs[b], __float_as_int(mv));
    }
}

// ---------------------------------------------------------------------------
// Kernel D: out *= rcp(max(max|harm| + 1e-7, 1)); 4 float4 per thread for MLP
// (best measured shape). Noise path is exactly zero.
// ---------------------------------------------------------------------------
__global__ void __launch_bounds__(256) kD(float4* __restrict__ out) {
    int b = blockIdx.y;
    float denom = fmaxf(__fadd_rn(__int_as_float(g_maxabs[b]), 1e-7f), 1.0f);
    float inv = __frcp_rn(denom);
    size_t base = (size_t)b * (NSAMP / 4) + blockIdx.x * 1024 + threadIdx.x;
    float4 v0 = out[base];
    float4 v1 = out[base + 256];
    float4 v2 = out[base + 512];
    float4 v3 = out[base + 768];
    v0.x *= inv; v0.y *= inv; v0.z *= inv; v0.w *= inv;
    v1.x *= inv; v1.y *= inv; v1.z *= inv; v1.w *= inv;
    v2.x *= inv; v2.y *= inv; v2.z *= inv; v2.w *= inv;
    v3.x *= inv; v3.y *= inv; v3.z *= inv; v3.w *= inv;
    out[base]       = v0;
    out[base + 256] = v1;
    out[base + 512] = v2;
    out[base + 768] = v3;
}

extern "C" void kernel_launch(void* const* d_in, const int* in_sizes, int n_in,
                              void* d_out, int out_size) {
    const float* f0 = (const float*)d_in[0];
    const float* ha = (const float*)d_in[1];
    float* out = (float*)d_out;

    kA<<<dim3(60, BATCH), 256>>>(f0);
    kB<<<BATCH, 256>>>();
    kC<<<dim3(960, BATCH), 256>>>(f0, ha, out);
    kD<<<dim3(60, BATCH), 256>>>((float4*)out);
}